// round 14
// baseline (speedup 1.0000x reference)
#include <cuda_runtime.h>
#include <cstdint>

// ============================================================================
// SensorCalibration. R14: R12's plain reduce (12.5us measured, no election)
// + adam kernel with smem-staged partial collapse (all 32 lanes sum the 8
// f32 partials into sM[17][81], then the loop reads LDS) to keep the
// 142-reg / 78.8us loop configuration of R13.
// Best so far: R12 = 94.8 (adam 81.8 @254r); R13 = 95.6 (adam 78.8 @142r,
// reduce +3.7us election tail).
// ============================================================================

#define NSENS 17
#define NT    16384
#define ROWLEN (NSENS * 9)
#define NBLK  8
#define NITER 450

__device__ float gPart[NSENS][NBLK][81];

// ---------------------------------------------------------------------------
// fast approx + packed f32x2 intrinsics
// ---------------------------------------------------------------------------
__device__ __forceinline__ float f_rsqrt(float x) { float r; asm("rsqrt.approx.f32 %0, %1;" : "=f"(r) : "f"(x)); return r; }
__device__ __forceinline__ float f_sin(float x)   { float r; asm("sin.approx.f32 %0, %1;"   : "=f"(r) : "f"(x)); return r; }
__device__ __forceinline__ float f_cos(float x)   { float r; asm("cos.approx.f32 %0, %1;"   : "=f"(r) : "f"(x)); return r; }
__device__ __forceinline__ float f_rcp(float x)   { float r; asm("rcp.approx.f32 %0, %1;"   : "=f"(r) : "f"(x)); return r; }
__device__ __forceinline__ float f_ex2(float x)   { float r; asm("ex2.approx.f32 %0, %1;"   : "=f"(r) : "f"(x)); return r; }

typedef unsigned long long u64;
__device__ __forceinline__ u64 pk2(float lo, float hi) {
    u64 r; asm("mov.b64 %0, {%1, %2};" : "=l"(r) : "f"(lo), "f"(hi)); return r;
}
__device__ __forceinline__ void upk2(float& lo, float& hi, u64 v) {
    asm("mov.b64 {%0, %1}, %2;" : "=f"(lo), "=f"(hi) : "l"(v));
}
__device__ __forceinline__ u64 fma2(u64 a, u64 b, u64 c) {
    u64 d; asm("fma.rn.f32x2 %0, %1, %2, %3;" : "=l"(d) : "l"(a), "l"(b), "l"(c)); return d;
}
__device__ __forceinline__ u64 mul2(u64 a, u64 b) {
    u64 d; asm("mul.rn.f32x2 %0, %1, %2;" : "=l"(d) : "l"(a), "l"(b)); return d;
}
__device__ __forceinline__ u64 add2(u64 a, u64 b) {
    u64 d; asm("add.rn.f32x2 %0, %1, %2;" : "=l"(d) : "l"(a), "l"(b)); return d;
}

// ---------------------------------------------------------------------------
// Kernel 1: per-block partials of M[n][jk][il] = sum_t org[t,n,jk]*trg[t,n,il]
// (R8/R12 version, measured 12.5us)
// ---------------------------------------------------------------------------
__global__ void reduce_kernel(const float* __restrict__ org,
                              const float* __restrict__ trg) {
    const int n    = blockIdx.y;
    const int base = blockIdx.x * blockDim.x + threadIdx.x;   // 0..2047

    u64   accP[9][4];
    float acc8[9];
#pragma unroll
    for (int j = 0; j < 9; j++) {
#pragma unroll
        for (int p = 0; p < 4; p++) accP[j][p] = 0ull;
        acc8[j] = 0.0f;
    }

#pragma unroll
    for (int kk = 0; kk < 8; kk++) {
        const int t = base + kk * 2048;
        const float* a = org + (size_t)t * ROWLEN + n * 9;
        const float* b = trg + (size_t)t * ROWLEN + n * 9;
        float av[9], bv[9];
#pragma unroll
        for (int i = 0; i < 9; i++) { av[i] = a[i]; bv[i] = b[i]; }
        u64 bp[4];
#pragma unroll
        for (int p = 0; p < 4; p++) bp[p] = pk2(bv[2 * p], bv[2 * p + 1]);
#pragma unroll
        for (int j = 0; j < 9; j++) {
            u64 ad = pk2(av[j], av[j]);
#pragma unroll
            for (int p = 0; p < 4; p++) accP[j][p] = fma2(ad, bp[p], accP[j][p]);
            acc8[j] = fmaf(av[j], bv[8], acc8[j]);
        }
    }

    const int lane = threadIdx.x & 31;
    const int wid  = threadIdx.x >> 5;
    __shared__ float sW[8][81];
#pragma unroll
    for (int j = 0; j < 9; j++) {
#pragma unroll
        for (int p = 0; p < 4; p++) {
            u64 v = accP[j][p];
#pragma unroll
            for (int d = 16; d >= 1; d >>= 1)
                v = add2(v, __shfl_xor_sync(0xFFFFFFFFu, v, d));
            if (lane == 0) {
                float lo, hi; upk2(lo, hi, v);
                sW[wid][j * 9 + 2 * p]     = lo;
                sW[wid][j * 9 + 2 * p + 1] = hi;
            }
        }
        float s8 = acc8[j];
#pragma unroll
        for (int d = 16; d >= 1; d >>= 1)
            s8 += __shfl_xor_sync(0xFFFFFFFFu, s8, d);
        if (lane == 0) sW[wid][j * 9 + 8] = s8;
    }
    __syncthreads();
    if (threadIdx.x < 81) {
        float s = 0.0f;
#pragma unroll
        for (int w = 0; w < 8; w++) s += sW[w][threadIdx.x];
        gPart[n][blockIdx.x][threadIdx.x] = s;
    }
}

// ---------------------------------------------------------------------------
// Threefry2x32-20, key (0,1), partitionable path: bits = o0 ^ o1.
// ---------------------------------------------------------------------------
__device__ __forceinline__ uint32_t rotl32(uint32_t v, uint32_t d) {
    return (v << d) | (v >> (32u - d));
}

__device__ void threefry_01(uint32_t x0, uint32_t x1, uint32_t& o0, uint32_t& o1) {
    const uint32_t k0 = 0u, k1 = 1u;
    const uint32_t k2 = k0 ^ k1 ^ 0x1BD11BDAu;
    x0 += k0; x1 += k1;
    x0 += x1; x1 = rotl32(x1, 13); x1 ^= x0;
    x0 += x1; x1 = rotl32(x1, 15); x1 ^= x0;
    x0 += x1; x1 = rotl32(x1, 26); x1 ^= x0;
    x0 += x1; x1 = rotl32(x1,  6); x1 ^= x0;
    x0 += k1; x1 += k2 + 1u;
    x0 += x1; x1 = rotl32(x1, 17); x1 ^= x0;
    x0 += x1; x1 = rotl32(x1, 29); x1 ^= x0;
    x0 += x1; x1 = rotl32(x1, 16); x1 ^= x0;
    x0 += x1; x1 = rotl32(x1, 24); x1 ^= x0;
    x0 += k2; x1 += k0 + 2u;
    x0 += x1; x1 = rotl32(x1, 13); x1 ^= x0;
    x0 += x1; x1 = rotl32(x1, 15); x1 ^= x0;
    x0 += x1; x1 = rotl32(x1, 26); x1 ^= x0;
    x0 += x1; x1 = rotl32(x1,  6); x1 ^= x0;
    x0 += k0; x1 += k1 + 3u;
    x0 += x1; x1 = rotl32(x1, 17); x1 ^= x0;
    x0 += x1; x1 = rotl32(x1, 29); x1 ^= x0;
    x0 += x1; x1 = rotl32(x1, 16); x1 ^= x0;
    x0 += x1; x1 = rotl32(x1, 24); x1 ^= x0;
    x0 += k1; x1 += k2 + 4u;
    x0 += x1; x1 = rotl32(x1, 13); x1 ^= x0;
    x0 += x1; x1 = rotl32(x1, 15); x1 ^= x0;
    x0 += x1; x1 = rotl32(x1, 26); x1 ^= x0;
    x0 += x1; x1 = rotl32(x1,  6); x1 ^= x0;
    x0 += k2; x1 += k0 + 5u;
    o0 = x0; o1 = x1;
}

__device__ float ang_init(int f) {
    uint32_t o0, o1;
    threefry_01(0u, (uint32_t)f, o0, o1);
    uint32_t bits = o0 ^ o1;
    uint32_t fb = (bits >> 9) | 0x3F800000u;
    return __uint_as_float(fb) - 1.0f;
}

// ---------------------------------------------------------------------------
// Kernel 2: 450 Adam iterations, one thread per sensor.
// Prologue: all 32 lanes collapse the 8 f32 partials into sM[17][81] (smem),
// keeping register pressure at the R13 level; loop = R11/R13 body.
// ---------------------------------------------------------------------------
__global__ void __launch_bounds__(32, 1) adam_kernel(float* __restrict__ out) {
    const int n = threadIdx.x;

    __shared__ float  sM[NSENS][81];
    __shared__ float2 sTab[NITER];

    // ---- cooperative partial collapse (b-order identical to R12) ----
    {
        const float* gp = &gPart[0][0][0];
        for (int i = threadIdx.x; i < NSENS * 81; i += 32) {
            int sn = i / 81;
            int e  = i - sn * 81;
            float s = 0.0f;
#pragma unroll
            for (int b = 0; b < NBLK; b++)
                s += gp[(sn * NBLK + b) * 81 + e];
            sM[sn][e] = s;
        }
    }

    // tab.x = lr_t * 0.1 / (1-0.9^t),  tab.y = 0.001 / (1-0.999^t)
    {
        const float l2_09   = -0.15200309344504997f;
        const float l2_0999 = -0.0014434504088372195f;
        for (int t = threadIdx.x; t < NITER; t += 32) {
            float tf = (float)(t + 1);
            float p1 = f_ex2(tf * l2_09);
            float p2 = f_ex2(tf * l2_0999);
            float lr = (t < 150) ? 0.01f : ((t < 300) ? 0.009f : 0.0081f);
            sTab[t].x = lr * 0.1f * f_rcp(1.0f - p1);
            sTab[t].y = 0.001f * f_rcp(1.0f - p2);
        }
    }
    __syncwarp();

    if (n >= NSENS) return;

    float Mdf[81];
#pragma unroll
    for (int e = 0; e < 81; e++) Mdf[e] = sM[n][e];

#define MSF(p, k, q, l) \
    (-20.0f * (Mdf[(3*(p)+(k))*9 + 3*(q)+(l)] + Mdf[(3*(k)+(p))*9 + 3*(l)+(q)]))

    float Fv[10][9];
#pragma unroll
    for (int k = 0; k < 3; k++)
#pragma unroll
        for (int l = 0; l < 3; l++) {
            int j = 3 * k + l;
            Fv[0][j] = MSF(0,k,0,l) + MSF(1,k,1,l) + MSF(2,k,2,l);   // T
            Fv[1][j] = MSF(2,k,1,l) - MSF(1,k,2,l);                  // Wx
            Fv[2][j] = MSF(0,k,2,l) - MSF(2,k,0,l);                  // Wy
            Fv[3][j] = MSF(1,k,0,l) - MSF(0,k,1,l);                  // Wz
            Fv[4][j] = 2.0f * MSF(0,k,0,l);                          // S00
            Fv[5][j] = MSF(0,k,1,l) + MSF(1,k,0,l);                  // S01
            Fv[6][j] = MSF(0,k,2,l) + MSF(2,k,0,l);                  // S02
            Fv[7][j] = 2.0f * MSF(1,k,1,l);                          // S11
            Fv[8][j] = MSF(1,k,2,l) + MSF(2,k,1,l);                  // S12
            Fv[9][j] = 2.0f * MSF(2,k,2,l);                          // S22
        }
#undef MSF

    u64 A0[5], BRc[5][3], QRc[5][6];
#pragma unroll
    for (int p = 0; p < 5; p++) {
        const float* lo = Fv[2 * p];
        const float* hi = Fv[2 * p + 1];
        A0[p]     = pk2(lo[0] + lo[4] + lo[8], hi[0] + hi[4] + hi[8]);
        BRc[p][0] = pk2(lo[7] - lo[5], hi[7] - hi[5]);
        BRc[p][1] = pk2(lo[2] - lo[6], hi[2] - hi[6]);
        BRc[p][2] = pk2(lo[3] - lo[1], hi[3] - hi[1]);
        QRc[p][0] = pk2(lo[0],         hi[0]);           // xx
        QRc[p][1] = pk2(lo[1] + lo[3], hi[1] + hi[3]);   // xy
        QRc[p][2] = pk2(lo[2] + lo[6], hi[2] + hi[6]);   // xz
        QRc[p][3] = pk2(lo[4],         hi[4]);           // yy
        QRc[p][4] = pk2(lo[5] + lo[7], hi[5] + hi[7]);   // yz
        QRc[p][5] = pk2(lo[8],         hi[8]);           // zz
    }

    float rx = ang_init(3 * n + 0);
    float ry = ang_init(3 * n + 1);
    float rz = ang_init(3 * n + 2);
    float Mx = 0.f, My = 0.f, Mz = 0.f;    // m / 0.1
    float Vx = 0.f, Vy = 0.f, Vz = 0.f;    // v / 0.001

#pragma unroll 1
    for (int it = 0; it < NITER; it++) {
        float2 tab = sTab[it];

        float th2 = fmaxf(fmaf(rx, rx, fmaf(ry, ry, rz * rz)), 1e-24f);
        float inv = f_rsqrt(th2);
        float th  = th2 * inv;
        float s = f_sin(th);
        float c = f_cos(th);

        // ---- r-only block (fills MUFU latency) ----
        u64 Rdx = pk2(rx, rx), Rdy = pk2(ry, ry), Rdz = pk2(rz, rz);
        u64 Mxx = mul2(Rdx, Rdx), Mxy = mul2(Rdx, Rdy), Mxz = mul2(Rdx, Rdz);
        u64 Myy = mul2(Rdy, Rdy), Myz = mul2(Rdy, Rdz), Mzz = mul2(Rdz, Rdz);

        u64 BR[5], QR[5];
#pragma unroll
        for (int p = 0; p < 5; p++)
            BR[p] = fma2(BRc[p][2], Rdz,
                    fma2(BRc[p][1], Rdy, mul2(BRc[p][0], Rdx)));
#pragma unroll
        for (int p = 0; p < 5; p++)
            QR[p] = fma2(QRc[p][5], Mzz,
                    fma2(QRc[p][4], Myz,
                    fma2(QRc[p][3], Myy,
                    fma2(QRc[p][2], Mxz,
                    fma2(QRc[p][1], Mxy, mul2(QRc[p][0], Mxx))))));

        // ---- trig-derived scalars ----
        float o    = 1.0f - c;
        float si   = s * inv;
        float inv2 = inv * inv;
        float oi2  = o * inv2;
        float oi   = o * inv;
        float inv3 = inv2 * inv;
        float f4   = fmaf(0.5f, s, -oi) * inv3;
        float f5   = (c - si) * inv2;
        u64 Cdup = pk2(c, c), SId = pk2(si, si), OId = pk2(oi2, oi2);

        // ---- combine ----
        float tD, wx, wy, wz, S00, S01, S02, S11, S12, S22;
        {
            u64 f0 = fma2(OId, QR[0], fma2(SId, BR[0], mul2(Cdup, A0[0])));
            u64 f1 = fma2(OId, QR[1], fma2(SId, BR[1], mul2(Cdup, A0[1])));
            u64 f2 = fma2(OId, QR[2], fma2(SId, BR[2], mul2(Cdup, A0[2])));
            u64 f3 = fma2(OId, QR[3], fma2(SId, BR[3], mul2(Cdup, A0[3])));
            u64 f4p = fma2(OId, QR[4], fma2(SId, BR[4], mul2(Cdup, A0[4])));
            upk2(tD,  wx,  f0);
            upk2(wy,  wz,  f1);
            upk2(S00, S01, f2);
            upk2(S02, S11, f3);
            upk2(S12, S22, f4p);
        }

        float Srx = fmaf(S00, rx, fmaf(S01, ry, S02 * rz));
        float Sry = fmaf(S01, rx, fmaf(S11, ry, S12 * rz));
        float Srz = fmaf(S02, rx, fmaf(S12, ry, S22 * rz));
        float wr  = fmaf(wx, rx, fmaf(wy, ry, wz * rz));
        float rSr = fmaf(rx, Srx, fmaf(ry, Sry, rz * Srz));

        float A = fmaf(-si, tD, fmaf(f5, wr, f4 * rSr));

        float gx = fmaf(rx, A, fmaf(si, wx, oi2 * Srx));
        float gy = fmaf(ry, A, fmaf(si, wy, oi2 * Sry));
        float gz = fmaf(rz, A, fmaf(si, wz, oi2 * Srz));

        Mx = fmaf(0.9f, Mx, gx);
        My = fmaf(0.9f, My, gy);
        Mz = fmaf(0.9f, Mz, gz);
        Vx = fmaf(0.999f, Vx, gx * gx);
        Vy = fmaf(0.999f, Vy, gy * gy);
        Vz = fmaf(0.999f, Vz, gz * gz);

        float rsx = f_rsqrt(fmaf(Vx, tab.y, 1e-30f));
        float rsy = f_rsqrt(fmaf(Vy, tab.y, 1e-30f));
        float rsz = f_rsqrt(fmaf(Vz, tab.y, 1e-30f));
        rx = fmaf(-(tab.x * Mx), rsx, rx);
        ry = fmaf(-(tab.x * My), rsy, ry);
        rz = fmaf(-(tab.x * Mz), rsz, rz);
    }

    out[3 * n + 0] = rx;
    out[3 * n + 1] = ry;
    out[3 * n + 2] = rz;
}

// ---------------------------------------------------------------------------
extern "C" void kernel_launch(void* const* d_in, const int* in_sizes, int n_in,
                              void* d_out, int out_size) {
    const float* org = (const float*)d_in[0];
    const float* trg = (const float*)d_in[1];
    float* out = (float*)d_out;

    reduce_kernel<<<dim3(NBLK, NSENS), 256>>>(org, trg);
    adam_kernel<<<1, 32>>>(out);
}

// round 15
// speedup vs baseline: 1.0788x; 1.0788x over previous
#include <cuda_runtime.h>
#include <cstdint>

// ============================================================================
// SensorCalibration. R15: R12 (best, 94.8us) with gPart rows padded 81->84 so
// the adam prologue can sum the 8 partials via 21x8 LDG.128 (float4) fully
// unrolled — removes ~2-2.5us of exposed L2 latency that made R12's adam
// 81.8 instead of 78.8. Everything else byte-identical to R12.
// Prologue-cost ledger: R12 per-thread scalar = +3.0us; R13 in-reduce
// election = +3.7us (reduce side); R14 smem staging = +12.8us (never again).
// ============================================================================

#define NSENS 17
#define NT    16384
#define ROWLEN (NSENS * 9)
#define NBLK  8
#define NITER 450
#define PROW  84                       // padded partial row (16B-aligned)

__device__ float gPart[NSENS][NBLK][PROW];

// ---------------------------------------------------------------------------
// fast approx + packed f32x2 intrinsics
// ---------------------------------------------------------------------------
__device__ __forceinline__ float f_rsqrt(float x) { float r; asm("rsqrt.approx.f32 %0, %1;" : "=f"(r) : "f"(x)); return r; }
__device__ __forceinline__ float f_sin(float x)   { float r; asm("sin.approx.f32 %0, %1;"   : "=f"(r) : "f"(x)); return r; }
__device__ __forceinline__ float f_cos(float x)   { float r; asm("cos.approx.f32 %0, %1;"   : "=f"(r) : "f"(x)); return r; }
__device__ __forceinline__ float f_rcp(float x)   { float r; asm("rcp.approx.f32 %0, %1;"   : "=f"(r) : "f"(x)); return r; }
__device__ __forceinline__ float f_ex2(float x)   { float r; asm("ex2.approx.f32 %0, %1;"   : "=f"(r) : "f"(x)); return r; }

typedef unsigned long long u64;
__device__ __forceinline__ u64 pk2(float lo, float hi) {
    u64 r; asm("mov.b64 %0, {%1, %2};" : "=l"(r) : "f"(lo), "f"(hi)); return r;
}
__device__ __forceinline__ void upk2(float& lo, float& hi, u64 v) {
    asm("mov.b64 {%0, %1}, %2;" : "=f"(lo), "=f"(hi) : "l"(v));
}
__device__ __forceinline__ u64 fma2(u64 a, u64 b, u64 c) {
    u64 d; asm("fma.rn.f32x2 %0, %1, %2, %3;" : "=l"(d) : "l"(a), "l"(b), "l"(c)); return d;
}
__device__ __forceinline__ u64 mul2(u64 a, u64 b) {
    u64 d; asm("mul.rn.f32x2 %0, %1, %2;" : "=l"(d) : "l"(a), "l"(b)); return d;
}
__device__ __forceinline__ u64 add2(u64 a, u64 b) {
    u64 d; asm("add.rn.f32x2 %0, %1, %2;" : "=l"(d) : "l"(a), "l"(b)); return d;
}

// ---------------------------------------------------------------------------
// Kernel 1: per-block partials of M[n][jk][il] = sum_t org[t,n,jk]*trg[t,n,il]
// (R8/R12 version, measured 12.5us; only the gPart row stride changed)
// ---------------------------------------------------------------------------
__global__ void reduce_kernel(const float* __restrict__ org,
                              const float* __restrict__ trg) {
    const int n    = blockIdx.y;
    const int base = blockIdx.x * blockDim.x + threadIdx.x;   // 0..2047

    u64   accP[9][4];
    float acc8[9];
#pragma unroll
    for (int j = 0; j < 9; j++) {
#pragma unroll
        for (int p = 0; p < 4; p++) accP[j][p] = 0ull;
        acc8[j] = 0.0f;
    }

#pragma unroll
    for (int kk = 0; kk < 8; kk++) {
        const int t = base + kk * 2048;
        const float* a = org + (size_t)t * ROWLEN + n * 9;
        const float* b = trg + (size_t)t * ROWLEN + n * 9;
        float av[9], bv[9];
#pragma unroll
        for (int i = 0; i < 9; i++) { av[i] = a[i]; bv[i] = b[i]; }
        u64 bp[4];
#pragma unroll
        for (int p = 0; p < 4; p++) bp[p] = pk2(bv[2 * p], bv[2 * p + 1]);
#pragma unroll
        for (int j = 0; j < 9; j++) {
            u64 ad = pk2(av[j], av[j]);
#pragma unroll
            for (int p = 0; p < 4; p++) accP[j][p] = fma2(ad, bp[p], accP[j][p]);
            acc8[j] = fmaf(av[j], bv[8], acc8[j]);
        }
    }

    const int lane = threadIdx.x & 31;
    const int wid  = threadIdx.x >> 5;
    __shared__ float sW[8][81];
#pragma unroll
    for (int j = 0; j < 9; j++) {
#pragma unroll
        for (int p = 0; p < 4; p++) {
            u64 v = accP[j][p];
#pragma unroll
            for (int d = 16; d >= 1; d >>= 1)
                v = add2(v, __shfl_xor_sync(0xFFFFFFFFu, v, d));
            if (lane == 0) {
                float lo, hi; upk2(lo, hi, v);
                sW[wid][j * 9 + 2 * p]     = lo;
                sW[wid][j * 9 + 2 * p + 1] = hi;
            }
        }
        float s8 = acc8[j];
#pragma unroll
        for (int d = 16; d >= 1; d >>= 1)
            s8 += __shfl_xor_sync(0xFFFFFFFFu, s8, d);
        if (lane == 0) sW[wid][j * 9 + 8] = s8;
    }
    __syncthreads();
    if (threadIdx.x < 84) {
        float s = 0.0f;
        if (threadIdx.x < 81) {
#pragma unroll
            for (int w = 0; w < 8; w++) s += sW[w][threadIdx.x];
        }
        // pad elements 81..83 written as 0 so float4 prologue reads are clean
        gPart[n][blockIdx.x][threadIdx.x] = s;
    }
}

// ---------------------------------------------------------------------------
// Threefry2x32-20, key (0,1), partitionable path: bits = o0 ^ o1.
// ---------------------------------------------------------------------------
__device__ __forceinline__ uint32_t rotl32(uint32_t v, uint32_t d) {
    return (v << d) | (v >> (32u - d));
}

__device__ void threefry_01(uint32_t x0, uint32_t x1, uint32_t& o0, uint32_t& o1) {
    const uint32_t k0 = 0u, k1 = 1u;
    const uint32_t k2 = k0 ^ k1 ^ 0x1BD11BDAu;
    x0 += k0; x1 += k1;
    x0 += x1; x1 = rotl32(x1, 13); x1 ^= x0;
    x0 += x1; x1 = rotl32(x1, 15); x1 ^= x0;
    x0 += x1; x1 = rotl32(x1, 26); x1 ^= x0;
    x0 += x1; x1 = rotl32(x1,  6); x1 ^= x0;
    x0 += k1; x1 += k2 + 1u;
    x0 += x1; x1 = rotl32(x1, 17); x1 ^= x0;
    x0 += x1; x1 = rotl32(x1, 29); x1 ^= x0;
    x0 += x1; x1 = rotl32(x1, 16); x1 ^= x0;
    x0 += x1; x1 = rotl32(x1, 24); x1 ^= x0;
    x0 += k2; x1 += k0 + 2u;
    x0 += x1; x1 = rotl32(x1, 13); x1 ^= x0;
    x0 += x1; x1 = rotl32(x1, 15); x1 ^= x0;
    x0 += x1; x1 = rotl32(x1, 26); x1 ^= x0;
    x0 += x1; x1 = rotl32(x1,  6); x1 ^= x0;
    x0 += k0; x1 += k1 + 3u;
    x0 += x1; x1 = rotl32(x1, 17); x1 ^= x0;
    x0 += x1; x1 = rotl32(x1, 29); x1 ^= x0;
    x0 += x1; x1 = rotl32(x1, 16); x1 ^= x0;
    x0 += x1; x1 = rotl32(x1, 24); x1 ^= x0;
    x0 += k1; x1 += k2 + 4u;
    x0 += x1; x1 = rotl32(x1, 13); x1 ^= x0;
    x0 += x1; x1 = rotl32(x1, 15); x1 ^= x0;
    x0 += x1; x1 = rotl32(x1, 26); x1 ^= x0;
    x0 += x1; x1 = rotl32(x1,  6); x1 ^= x0;
    x0 += k2; x1 += k0 + 5u;
    o0 = x0; o1 = x1;
}

__device__ float ang_init(int f) {
    uint32_t o0, o1;
    threefry_01(0u, (uint32_t)f, o0, o1);
    uint32_t bits = o0 ^ o1;
    uint32_t fb = (bits >> 9) | 0x3F800000u;
    return __uint_as_float(fb) - 1.0f;
}

// ---------------------------------------------------------------------------
// Kernel 2: 450 Adam iterations, one thread per sensor.
// Prologue: float4 (LDG.128) sum of the 8 partials, fully unrolled for MLP;
// loop identical to R12/R13 math.
// ---------------------------------------------------------------------------
__global__ void __launch_bounds__(32, 1) adam_kernel(float* __restrict__ out) {
    const int n = threadIdx.x;

    // tab.x = lr_t * 0.1 / (1-0.9^t),  tab.y = 0.001 / (1-0.999^t)
    __shared__ float2 sTab[NITER];
    {
        const float l2_09   = -0.15200309344504997f;
        const float l2_0999 = -0.0014434504088372195f;
        for (int t = threadIdx.x; t < NITER; t += 32) {
            float tf = (float)(t + 1);
            float p1 = f_ex2(tf * l2_09);
            float p2 = f_ex2(tf * l2_0999);
            float lr = (t < 150) ? 0.01f : ((t < 300) ? 0.009f : 0.0081f);
            sTab[t].x = lr * 0.1f * f_rcp(1.0f - p1);
            sTab[t].y = 0.001f * f_rcp(1.0f - p2);
        }
    }
    __syncwarp();

    if (n >= NSENS) return;

    // vectorized f32 sum of the 8 per-block partials (21 float4 per block)
    float Mdf[PROW];
    {
        const float4* gp4 = reinterpret_cast<const float4*>(&gPart[n][0][0]);
#pragma unroll
        for (int q = 0; q < PROW / 4; q++) {
            float4 s0 = gp4[q];
            float sx = s0.x, sy = s0.y, sz = s0.z, sw = s0.w;
#pragma unroll
            for (int b = 1; b < NBLK; b++) {
                float4 t4 = gp4[b * (PROW / 4) + q];
                sx += t4.x; sy += t4.y; sz += t4.z; sw += t4.w;
            }
            Mdf[4 * q + 0] = sx;
            Mdf[4 * q + 1] = sy;
            Mdf[4 * q + 2] = sz;
            Mdf[4 * q + 3] = sw;
        }
    }

#define MSF(p, k, q, l) \
    (-20.0f * (Mdf[(3*(p)+(k))*9 + 3*(q)+(l)] + Mdf[(3*(k)+(p))*9 + 3*(l)+(q)]))

    float Fv[10][9];
#pragma unroll
    for (int k = 0; k < 3; k++)
#pragma unroll
        for (int l = 0; l < 3; l++) {
            int j = 3 * k + l;
            Fv[0][j] = MSF(0,k,0,l) + MSF(1,k,1,l) + MSF(2,k,2,l);   // T
            Fv[1][j] = MSF(2,k,1,l) - MSF(1,k,2,l);                  // Wx
            Fv[2][j] = MSF(0,k,2,l) - MSF(2,k,0,l);                  // Wy
            Fv[3][j] = MSF(1,k,0,l) - MSF(0,k,1,l);                  // Wz
            Fv[4][j] = 2.0f * MSF(0,k,0,l);                          // S00
            Fv[5][j] = MSF(0,k,1,l) + MSF(1,k,0,l);                  // S01
            Fv[6][j] = MSF(0,k,2,l) + MSF(2,k,0,l);                  // S02
            Fv[7][j] = 2.0f * MSF(1,k,1,l);                          // S11
            Fv[8][j] = MSF(1,k,2,l) + MSF(2,k,1,l);                  // S12
            Fv[9][j] = 2.0f * MSF(2,k,2,l);                          // S22
        }
#undef MSF

    u64 A0[5], BRc[5][3], QRc[5][6];
#pragma unroll
    for (int p = 0; p < 5; p++) {
        const float* lo = Fv[2 * p];
        const float* hi = Fv[2 * p + 1];
        A0[p]     = pk2(lo[0] + lo[4] + lo[8], hi[0] + hi[4] + hi[8]);
        BRc[p][0] = pk2(lo[7] - lo[5], hi[7] - hi[5]);
        BRc[p][1] = pk2(lo[2] - lo[6], hi[2] - hi[6]);
        BRc[p][2] = pk2(lo[3] - lo[1], hi[3] - hi[1]);
        QRc[p][0] = pk2(lo[0],         hi[0]);           // xx
        QRc[p][1] = pk2(lo[1] + lo[3], hi[1] + hi[3]);   // xy
        QRc[p][2] = pk2(lo[2] + lo[6], hi[2] + hi[6]);   // xz
        QRc[p][3] = pk2(lo[4],         hi[4]);           // yy
        QRc[p][4] = pk2(lo[5] + lo[7], hi[5] + hi[7]);   // yz
        QRc[p][5] = pk2(lo[8],         hi[8]);           // zz
    }

    float rx = ang_init(3 * n + 0);
    float ry = ang_init(3 * n + 1);
    float rz = ang_init(3 * n + 2);
    float Mx = 0.f, My = 0.f, Mz = 0.f;    // m / 0.1
    float Vx = 0.f, Vy = 0.f, Vz = 0.f;    // v / 0.001

#pragma unroll 1
    for (int it = 0; it < NITER; it++) {
        float2 tab = sTab[it];

        float th2 = fmaxf(fmaf(rx, rx, fmaf(ry, ry, rz * rz)), 1e-24f);
        float inv = f_rsqrt(th2);
        float th  = th2 * inv;
        float s = f_sin(th);
        float c = f_cos(th);

        // ---- r-only block (fills MUFU latency) ----
        u64 Rdx = pk2(rx, rx), Rdy = pk2(ry, ry), Rdz = pk2(rz, rz);
        u64 Mxx = mul2(Rdx, Rdx), Mxy = mul2(Rdx, Rdy), Mxz = mul2(Rdx, Rdz);
        u64 Myy = mul2(Rdy, Rdy), Myz = mul2(Rdy, Rdz), Mzz = mul2(Rdz, Rdz);

        u64 BR[5], QR[5];
#pragma unroll
        for (int p = 0; p < 5; p++)
            BR[p] = fma2(BRc[p][2], Rdz,
                    fma2(BRc[p][1], Rdy, mul2(BRc[p][0], Rdx)));
#pragma unroll
        for (int p = 0; p < 5; p++)
            QR[p] = fma2(QRc[p][5], Mzz,
                    fma2(QRc[p][4], Myz,
                    fma2(QRc[p][3], Myy,
                    fma2(QRc[p][2], Mxz,
                    fma2(QRc[p][1], Mxy, mul2(QRc[p][0], Mxx))))));

        // ---- trig-derived scalars ----
        float o    = 1.0f - c;
        float si   = s * inv;
        float inv2 = inv * inv;
        float oi2  = o * inv2;
        float oi   = o * inv;
        float inv3 = inv2 * inv;
        float f4   = fmaf(0.5f, s, -oi) * inv3;
        float f5   = (c - si) * inv2;
        u64 Cdup = pk2(c, c), SId = pk2(si, si), OId = pk2(oi2, oi2);

        // ---- combine ----
        float tD, wx, wy, wz, S00, S01, S02, S11, S12, S22;
        {
            u64 f0 = fma2(OId, QR[0], fma2(SId, BR[0], mul2(Cdup, A0[0])));
            u64 f1 = fma2(OId, QR[1], fma2(SId, BR[1], mul2(Cdup, A0[1])));
            u64 f2 = fma2(OId, QR[2], fma2(SId, BR[2], mul2(Cdup, A0[2])));
            u64 f3 = fma2(OId, QR[3], fma2(SId, BR[3], mul2(Cdup, A0[3])));
            u64 f4p = fma2(OId, QR[4], fma2(SId, BR[4], mul2(Cdup, A0[4])));
            upk2(tD,  wx,  f0);
            upk2(wy,  wz,  f1);
            upk2(S00, S01, f2);
            upk2(S02, S11, f3);
            upk2(S12, S22, f4p);
        }

        float Srx = fmaf(S00, rx, fmaf(S01, ry, S02 * rz));
        float Sry = fmaf(S01, rx, fmaf(S11, ry, S12 * rz));
        float Srz = fmaf(S02, rx, fmaf(S12, ry, S22 * rz));
        float wr  = fmaf(wx, rx, fmaf(wy, ry, wz * rz));
        float rSr = fmaf(rx, Srx, fmaf(ry, Sry, rz * Srz));

        float A = fmaf(-si, tD, fmaf(f5, wr, f4 * rSr));

        float gx = fmaf(rx, A, fmaf(si, wx, oi2 * Srx));
        float gy = fmaf(ry, A, fmaf(si, wy, oi2 * Sry));
        float gz = fmaf(rz, A, fmaf(si, wz, oi2 * Srz));

        Mx = fmaf(0.9f, Mx, gx);
        My = fmaf(0.9f, My, gy);
        Mz = fmaf(0.9f, Mz, gz);
        Vx = fmaf(0.999f, Vx, gx * gx);
        Vy = fmaf(0.999f, Vy, gy * gy);
        Vz = fmaf(0.999f, Vz, gz * gz);

        float rsx = f_rsqrt(fmaf(Vx, tab.y, 1e-30f));
        float rsy = f_rsqrt(fmaf(Vy, tab.y, 1e-30f));
        float rsz = f_rsqrt(fmaf(Vz, tab.y, 1e-30f));
        rx = fmaf(-(tab.x * Mx), rsx, rx);
        ry = fmaf(-(tab.x * My), rsy, ry);
        rz = fmaf(-(tab.x * Mz), rsz, rz);
    }

    out[3 * n + 0] = rx;
    out[3 * n + 1] = ry;
    out[3 * n + 2] = rz;
}

// ---------------------------------------------------------------------------
extern "C" void kernel_launch(void* const* d_in, const int* in_sizes, int n_in,
                              void* d_out, int out_size) {
    const float* org = (const float*)d_in[0];
    const float* trg = (const float*)d_in[1];
    float* out = (float*)d_out;

    reduce_kernel<<<dim3(NBLK, NSENS), 256>>>(org, trg);
    adam_kernel<<<1, 32>>>(out);
}

// round 16
// speedup vs baseline: 1.2185x; 1.1295x over previous
#include <cuda_runtime.h>
#include <cstdint>

// ============================================================================
// SensorCalibration. R16: lane-parallel adam — one BLOCK per sensor (17x32),
// the 10 functionals computed one-per-lane (12 warp-instructions vs ~60
// packed slots), shfl broadcast, lane-uniform tail. Arithmetic and op-order
// bitwise-identical to R15. Reduce kernel = R15 verbatim.
// R15 best: 92.96 (adam 80.2, reduce ~12.8).
// ============================================================================

#define NSENS 17
#define NT    16384
#define ROWLEN (NSENS * 9)
#define NBLK  8
#define NITER 450
#define PROW  84                       // padded partial row (16B-aligned)

__device__ float gPart[NSENS][NBLK][PROW];

// ---------------------------------------------------------------------------
// fast approx + packed f32x2 intrinsics
// ---------------------------------------------------------------------------
__device__ __forceinline__ float f_rsqrt(float x) { float r; asm("rsqrt.approx.f32 %0, %1;" : "=f"(r) : "f"(x)); return r; }
__device__ __forceinline__ float f_sin(float x)   { float r; asm("sin.approx.f32 %0, %1;"   : "=f"(r) : "f"(x)); return r; }
__device__ __forceinline__ float f_cos(float x)   { float r; asm("cos.approx.f32 %0, %1;"   : "=f"(r) : "f"(x)); return r; }
__device__ __forceinline__ float f_rcp(float x)   { float r; asm("rcp.approx.f32 %0, %1;"   : "=f"(r) : "f"(x)); return r; }
__device__ __forceinline__ float f_ex2(float x)   { float r; asm("ex2.approx.f32 %0, %1;"   : "=f"(r) : "f"(x)); return r; }

typedef unsigned long long u64;
__device__ __forceinline__ u64 pk2(float lo, float hi) {
    u64 r; asm("mov.b64 %0, {%1, %2};" : "=l"(r) : "f"(lo), "f"(hi)); return r;
}
__device__ __forceinline__ void upk2(float& lo, float& hi, u64 v) {
    asm("mov.b64 {%0, %1}, %2;" : "=f"(lo), "=f"(hi) : "l"(v));
}
__device__ __forceinline__ u64 fma2(u64 a, u64 b, u64 c) {
    u64 d; asm("fma.rn.f32x2 %0, %1, %2, %3;" : "=l"(d) : "l"(a), "l"(b), "l"(c)); return d;
}
__device__ __forceinline__ u64 add2(u64 a, u64 b) {
    u64 d; asm("add.rn.f32x2 %0, %1, %2;" : "=l"(d) : "l"(a), "l"(b)); return d;
}

// ---------------------------------------------------------------------------
// Kernel 1: per-block partials (R15 verbatim, measured ~12.5us)
// ---------------------------------------------------------------------------
__global__ void reduce_kernel(const float* __restrict__ org,
                              const float* __restrict__ trg) {
    const int n    = blockIdx.y;
    const int base = blockIdx.x * blockDim.x + threadIdx.x;   // 0..2047

    u64   accP[9][4];
    float acc8[9];
#pragma unroll
    for (int j = 0; j < 9; j++) {
#pragma unroll
        for (int p = 0; p < 4; p++) accP[j][p] = 0ull;
        acc8[j] = 0.0f;
    }

#pragma unroll
    for (int kk = 0; kk < 8; kk++) {
        const int t = base + kk * 2048;
        const float* a = org + (size_t)t * ROWLEN + n * 9;
        const float* b = trg + (size_t)t * ROWLEN + n * 9;
        float av[9], bv[9];
#pragma unroll
        for (int i = 0; i < 9; i++) { av[i] = a[i]; bv[i] = b[i]; }
        u64 bp[4];
#pragma unroll
        for (int p = 0; p < 4; p++) bp[p] = pk2(bv[2 * p], bv[2 * p + 1]);
#pragma unroll
        for (int j = 0; j < 9; j++) {
            u64 ad = pk2(av[j], av[j]);
#pragma unroll
            for (int p = 0; p < 4; p++) accP[j][p] = fma2(ad, bp[p], accP[j][p]);
            acc8[j] = fmaf(av[j], bv[8], acc8[j]);
        }
    }

    const int lane = threadIdx.x & 31;
    const int wid  = threadIdx.x >> 5;
    __shared__ float sW[8][81];
#pragma unroll
    for (int j = 0; j < 9; j++) {
#pragma unroll
        for (int p = 0; p < 4; p++) {
            u64 v = accP[j][p];
#pragma unroll
            for (int d = 16; d >= 1; d >>= 1)
                v = add2(v, __shfl_xor_sync(0xFFFFFFFFu, v, d));
            if (lane == 0) {
                float lo, hi; upk2(lo, hi, v);
                sW[wid][j * 9 + 2 * p]     = lo;
                sW[wid][j * 9 + 2 * p + 1] = hi;
            }
        }
        float s8 = acc8[j];
#pragma unroll
        for (int d = 16; d >= 1; d >>= 1)
            s8 += __shfl_xor_sync(0xFFFFFFFFu, s8, d);
        if (lane == 0) sW[wid][j * 9 + 8] = s8;
    }
    __syncthreads();
    if (threadIdx.x < 84) {
        float s = 0.0f;
        if (threadIdx.x < 81) {
#pragma unroll
            for (int w = 0; w < 8; w++) s += sW[w][threadIdx.x];
        }
        gPart[n][blockIdx.x][threadIdx.x] = s;
    }
}

// ---------------------------------------------------------------------------
// Threefry2x32-20, key (0,1), partitionable path: bits = o0 ^ o1.
// ---------------------------------------------------------------------------
__device__ __forceinline__ uint32_t rotl32(uint32_t v, uint32_t d) {
    return (v << d) | (v >> (32u - d));
}

__device__ void threefry_01(uint32_t x0, uint32_t x1, uint32_t& o0, uint32_t& o1) {
    const uint32_t k0 = 0u, k1 = 1u;
    const uint32_t k2 = k0 ^ k1 ^ 0x1BD11BDAu;
    x0 += k0; x1 += k1;
    x0 += x1; x1 = rotl32(x1, 13); x1 ^= x0;
    x0 += x1; x1 = rotl32(x1, 15); x1 ^= x0;
    x0 += x1; x1 = rotl32(x1, 26); x1 ^= x0;
    x0 += x1; x1 = rotl32(x1,  6); x1 ^= x0;
    x0 += k1; x1 += k2 + 1u;
    x0 += x1; x1 = rotl32(x1, 17); x1 ^= x0;
    x0 += x1; x1 = rotl32(x1, 29); x1 ^= x0;
    x0 += x1; x1 = rotl32(x1, 16); x1 ^= x0;
    x0 += x1; x1 = rotl32(x1, 24); x1 ^= x0;
    x0 += k2; x1 += k0 + 2u;
    x0 += x1; x1 = rotl32(x1, 13); x1 ^= x0;
    x0 += x1; x1 = rotl32(x1, 15); x1 ^= x0;
    x0 += x1; x1 = rotl32(x1, 26); x1 ^= x0;
    x0 += x1; x1 = rotl32(x1,  6); x1 ^= x0;
    x0 += k0; x1 += k1 + 3u;
    x0 += x1; x1 = rotl32(x1, 17); x1 ^= x0;
    x0 += x1; x1 = rotl32(x1, 29); x1 ^= x0;
    x0 += x1; x1 = rotl32(x1, 16); x1 ^= x0;
    x0 += x1; x1 = rotl32(x1, 24); x1 ^= x0;
    x0 += k1; x1 += k2 + 4u;
    x0 += x1; x1 = rotl32(x1, 13); x1 ^= x0;
    x0 += x1; x1 = rotl32(x1, 15); x1 ^= x0;
    x0 += x1; x1 = rotl32(x1, 26); x1 ^= x0;
    x0 += x1; x1 = rotl32(x1,  6); x1 ^= x0;
    x0 += k2; x1 += k0 + 5u;
    o0 = x0; o1 = x1;
}

__device__ float ang_init(int f) {
    uint32_t o0, o1;
    threefry_01(0u, (uint32_t)f, o0, o1);
    uint32_t bits = o0 ^ o1;
    uint32_t fb = (bits >> 9) | 0x3F800000u;
    return __uint_as_float(fb) - 1.0f;
}

// ---------------------------------------------------------------------------
// Kernel 2: 450 Adam iterations. One BLOCK (1 warp) per sensor; lane l<10
// evaluates functional l (a0 + b.r + r^T Q r), shfl broadcasts the 10
// scalars, tail is lane-uniform. Ops/order bitwise-identical to R15.
// ---------------------------------------------------------------------------
__global__ void __launch_bounds__(32, 1) adam_kernel(float* __restrict__ out) {
    const int n    = blockIdx.x;      // sensor
    const int lane = threadIdx.x;

    __shared__ float  sCoef[10][10];  // [func][a0, b0..b2, q0..q5]
    __shared__ float2 sTab[NITER];

    // table: tab.x = lr*0.1/(1-0.9^t), tab.y = 0.001/(1-0.999^t)
    {
        const float l2_09   = -0.15200309344504997f;
        const float l2_0999 = -0.0014434504088372195f;
        for (int t = lane; t < NITER; t += 32) {
            float tf = (float)(t + 1);
            float p1 = f_ex2(tf * l2_09);
            float p2 = f_ex2(tf * l2_0999);
            float lr = (t < 150) ? 0.01f : ((t < 300) ? 0.009f : 0.0081f);
            sTab[t].x = lr * 0.1f * f_rcp(1.0f - p1);
            sTab[t].y = 0.001f * f_rcp(1.0f - p2);
        }
    }

    // prologue (lane 0 only): float4 sum of partials, functionals, coeffs.
    if (lane == 0) {
        float Mdf[PROW];
        const float4* gp4 = reinterpret_cast<const float4*>(&gPart[n][0][0]);
#pragma unroll
        for (int q = 0; q < PROW / 4; q++) {
            float4 s0 = gp4[q];
            float sx = s0.x, sy = s0.y, sz = s0.z, sw = s0.w;
#pragma unroll
            for (int b = 1; b < NBLK; b++) {
                float4 t4 = gp4[b * (PROW / 4) + q];
                sx += t4.x; sy += t4.y; sz += t4.z; sw += t4.w;
            }
            Mdf[4 * q + 0] = sx;
            Mdf[4 * q + 1] = sy;
            Mdf[4 * q + 2] = sz;
            Mdf[4 * q + 3] = sw;
        }

#define MSF(p, k, q, l) \
    (-20.0f * (Mdf[(3*(p)+(k))*9 + 3*(q)+(l)] + Mdf[(3*(k)+(p))*9 + 3*(l)+(q)]))

        float Fv[10][9];
#pragma unroll
        for (int k = 0; k < 3; k++)
#pragma unroll
            for (int l = 0; l < 3; l++) {
                int j = 3 * k + l;
                Fv[0][j] = MSF(0,k,0,l) + MSF(1,k,1,l) + MSF(2,k,2,l);   // T
                Fv[1][j] = MSF(2,k,1,l) - MSF(1,k,2,l);                  // Wx
                Fv[2][j] = MSF(0,k,2,l) - MSF(2,k,0,l);                  // Wy
                Fv[3][j] = MSF(1,k,0,l) - MSF(0,k,1,l);                  // Wz
                Fv[4][j] = 2.0f * MSF(0,k,0,l);                          // S00
                Fv[5][j] = MSF(0,k,1,l) + MSF(1,k,0,l);                  // S01
                Fv[6][j] = MSF(0,k,2,l) + MSF(2,k,0,l);                  // S02
                Fv[7][j] = 2.0f * MSF(1,k,1,l);                          // S11
                Fv[8][j] = MSF(1,k,2,l) + MSF(2,k,1,l);                  // S12
                Fv[9][j] = 2.0f * MSF(2,k,2,l);                          // S22
            }
#undef MSF

#pragma unroll
        for (int p = 0; p < 10; p++) {
            const float* F = Fv[p];
            sCoef[p][0] = F[0] + F[4] + F[8];    // a0
            sCoef[p][1] = F[7] - F[5];           // b0
            sCoef[p][2] = F[2] - F[6];           // b1
            sCoef[p][3] = F[3] - F[1];           // b2
            sCoef[p][4] = F[0];                  // q: xx
            sCoef[p][5] = F[1] + F[3];           //    xy
            sCoef[p][6] = F[2] + F[6];           //    xz
            sCoef[p][7] = F[4];                  //    yy
            sCoef[p][8] = F[5] + F[7];           //    yz
            sCoef[p][9] = F[8];                  //    zz
        }
    }
    __syncwarp();

    // per-lane coefficients (lanes >=10 mirror lane 9; their F is unused)
    const int lc = (lane < 10) ? lane : 9;
    const float ca0 = sCoef[lc][0];
    const float cb0 = sCoef[lc][1], cb1 = sCoef[lc][2], cb2 = sCoef[lc][3];
    const float cq0 = sCoef[lc][4], cq1 = sCoef[lc][5], cq2 = sCoef[lc][6];
    const float cq3 = sCoef[lc][7], cq4 = sCoef[lc][8], cq5 = sCoef[lc][9];

    // lane-uniform state
    float rx = ang_init(3 * n + 0);
    float ry = ang_init(3 * n + 1);
    float rz = ang_init(3 * n + 2);
    float Mx = 0.f, My = 0.f, Mz = 0.f;    // m / 0.1
    float Vx = 0.f, Vy = 0.f, Vz = 0.f;    // v / 0.001

#pragma unroll 1
    for (int it = 0; it < NITER; it++) {
        float2 tab = sTab[it];

        float th2 = fmaxf(fmaf(rx, rx, fmaf(ry, ry, rz * rz)), 1e-24f);
        float inv = f_rsqrt(th2);
        float th  = th2 * inv;
        float s = f_sin(th);
        float c = f_cos(th);

        // r-only monomials (uniform)
        float xx = rx * rx, xy = rx * ry, xz = rx * rz;
        float yy = ry * ry, yz = ry * rz, zz = rz * rz;

        // per-lane functional evaluation (12 warp-instructions)
        float br = fmaf(cb2, rz, fmaf(cb1, ry, cb0 * rx));
        float qr = fmaf(cq5, zz, fmaf(cq4, yz, fmaf(cq3, yy,
                   fmaf(cq2, xz, fmaf(cq1, xy, cq0 * xx)))));

        float o    = 1.0f - c;
        float si   = s * inv;
        float inv2 = inv * inv;
        float oi2  = o * inv2;
        float oi   = o * inv;
        float inv3 = inv2 * inv;
        float f4   = fmaf(0.5f, s, -oi) * inv3;
        float f5   = (c - si) * inv2;

        float F = fmaf(oi2, qr, fmaf(si, br, c * ca0));

        // broadcast the 10 functional values
        float tD  = __shfl_sync(0xFFFFFFFFu, F, 0);
        float wx  = __shfl_sync(0xFFFFFFFFu, F, 1);
        float wy  = __shfl_sync(0xFFFFFFFFu, F, 2);
        float wz  = __shfl_sync(0xFFFFFFFFu, F, 3);
        float S00 = __shfl_sync(0xFFFFFFFFu, F, 4);
        float S01 = __shfl_sync(0xFFFFFFFFu, F, 5);
        float S02 = __shfl_sync(0xFFFFFFFFu, F, 6);
        float S11 = __shfl_sync(0xFFFFFFFFu, F, 7);
        float S12 = __shfl_sync(0xFFFFFFFFu, F, 8);
        float S22 = __shfl_sync(0xFFFFFFFFu, F, 9);

        // lane-uniform tail (identical to R15)
        float Srx = fmaf(S00, rx, fmaf(S01, ry, S02 * rz));
        float Sry = fmaf(S01, rx, fmaf(S11, ry, S12 * rz));
        float Srz = fmaf(S02, rx, fmaf(S12, ry, S22 * rz));
        float wr  = fmaf(wx, rx, fmaf(wy, ry, wz * rz));
        float rSr = fmaf(rx, Srx, fmaf(ry, Sry, rz * Srz));

        float A = fmaf(-si, tD, fmaf(f5, wr, f4 * rSr));

        float gx = fmaf(rx, A, fmaf(si, wx, oi2 * Srx));
        float gy = fmaf(ry, A, fmaf(si, wy, oi2 * Sry));
        float gz = fmaf(rz, A, fmaf(si, wz, oi2 * Srz));

        Mx = fmaf(0.9f, Mx, gx);
        My = fmaf(0.9f, My, gy);
        Mz = fmaf(0.9f, Mz, gz);
        Vx = fmaf(0.999f, Vx, gx * gx);
        Vy = fmaf(0.999f, Vy, gy * gy);
        Vz = fmaf(0.999f, Vz, gz * gz);

        float rsx = f_rsqrt(fmaf(Vx, tab.y, 1e-30f));
        float rsy = f_rsqrt(fmaf(Vy, tab.y, 1e-30f));
        float rsz = f_rsqrt(fmaf(Vz, tab.y, 1e-30f));
        rx = fmaf(-(tab.x * Mx), rsx, rx);
        ry = fmaf(-(tab.x * My), rsy, ry);
        rz = fmaf(-(tab.x * Mz), rsz, rz);
    }

    if (lane == 0) {
        out[3 * n + 0] = rx;
        out[3 * n + 1] = ry;
        out[3 * n + 2] = rz;
    }
}

// ---------------------------------------------------------------------------
extern "C" void kernel_launch(void* const* d_in, const int* in_sizes, int n_in,
                              void* d_out, int out_size) {
    const float* org = (const float*)d_in[0];
    const float* trg = (const float*)d_in[1];
    float* out = (float*)d_out;

    reduce_kernel<<<dim3(NBLK, NSENS), 256>>>(org, trg);
    adam_kernel<<<NSENS, 32>>>(out);
}